// round 17
// baseline (speedup 1.0000x reference)
#include <cuda_runtime.h>

// Problem constants (fixed by setup_inputs)
#define B_     8
#define N_     3072
#define D_     1024
#define D4_    256          // D/4 (float4)
#define STEPS  1024         // N/POOL
#define POOL_  3
#define NCH    64           // chunks per batch
#define CWIN   16           // windows per chunk
#define EPS_   0.006f

// Scratch (__device__ globals; no allocations allowed)
__device__ float g_L [(size_t)B_ * (STEPS + 1) * D_];  // chunk-local exclusive window prefix
__device__ float g_S [(size_t)B_ * NCH * D_];          // chunk totals
__device__ float g_SP[(size_t)B_ * (NCH + 1) * D_];    // exclusive scan of chunk totals
__device__ int4  g_idx[B_ * STEPS];                    // packed (qe,resE,qs,resS)
__device__ float g_inv[B_ * STEPS];                    // 1/len per segment

__device__ __forceinline__ float4 f4add(float4 a, float4 b) {
    return make_float4(a.x + b.x, a.y + b.y, a.z + b.z, a.w + b.w);
}
__device__ __forceinline__ float4 f4sub(float4 a, float4 b) {
    return make_float4(a.x - b.x, a.y - b.y, a.z - b.z, a.w - b.w);
}
__device__ __forceinline__ float4 ldcs4(const float4* p) { return __ldcs(p); }
__device__ __forceinline__ void stcs4(float4* p, float4 v) { __stcs(p, v); }

// ---------------------------------------------------------------------------
// 0) Prep (stream 2, overlapped with k_fused; touches only graph): per-block
//    dtype detection + index precompute (ceiling trick).
//    int64 LE => odd 32-bit words are zero high halves; int32 => 256 random
//    e's per block, ~never all zero.
//    Residual encoding: 0 = none, +(row+1) = add x row, -(row+1) = subtract.
// ---------------------------------------------------------------------------
__global__ void __launch_bounds__(256) k_prep(const void* __restrict__ graph) {
    __shared__ unsigned int sh[256];
    __shared__ int is32;
    int t = threadIdx.x;
    int bt = blockIdx.x * 256 + t;               // 0..8191

    const unsigned int* g32 = (const unsigned int*)graph;
    sh[t] = g32[(size_t)blockIdx.x * 512 + 2 * t + 1];
    __syncthreads();
    for (int o = 128; o > 0; o >>= 1) {
        if (t < o) sh[t] |= sh[t + o];
        __syncthreads();
    }
    if (t == 0) is32 = (sh[0] != 0u) ? 1 : 0;
    __syncthreads();

    int s, e;
    if (is32) {
        int2 v = ((const int2*)graph)[bt];
        s = v.x; e = v.y;
    } else {
        longlong2 v = ((const longlong2*)graph)[bt];
        s = (int)v.x; e = (int)v.y;
    }
    int ke = e + 1, ks = s;
    int qe = ke / 3, re = ke - 3 * qe, resE = 0;       // end boundary (added)
    if (re == 1) resE = (3 * qe) + 1;                                  // + x[3q]
    else if (re == 2) { qe += 1; resE = -((3 * (qe - 1) + 2) + 1); }   // - x[3q+2]
    int qs = ks / 3, rs = ks - 3 * qs, resS = 0;       // start boundary (subtracted)
    if (rs == 1) resS = -((3 * qs) + 1);                               // - x[3q]
    else if (rs == 2) { qs += 1; resS = (3 * (qs - 1) + 2) + 1; }      // + x[3q+2]
    g_idx[bt] = make_int4(qe, resE, qs, resS);
    g_inv[bt] = 1.0f / (float)(ke - ks);
}

// ---------------------------------------------------------------------------
// 1) Fused pass over x (streamed), depth-2 register pipeline. Writes ONLY the
//    chunk-local exclusive prefix L (L2-resident) and chunk totals S.
// ---------------------------------------------------------------------------
__global__ void __launch_bounds__(256) k_fused(const float4* __restrict__ x) {
    int blk = blockIdx.x;               // B*NCH = 512 blocks
    int b = blk >> 6, c = blk & 63;
    int q0 = c * CWIN;
    int i = threadIdx.x;

    const float4* xr = x + ((size_t)(b * N_ + POOL_ * q0)) * D4_ + i;
    float4* L4 = (float4*)g_L + ((size_t)b * (STEPS + 1) + q0) * D4_ + i;

    float4 run = make_float4(0.f, 0.f, 0.f, 0.f);

    // pipeline prologue: windows 0 and 1 in flight
    float4 A0 = ldcs4(&xr[0]);
    float4 B0 = ldcs4(&xr[(size_t)1 * D4_]);
    float4 C0 = ldcs4(&xr[(size_t)2 * D4_]);
    float4 A1 = ldcs4(&xr[(size_t)3 * D4_]);
    float4 B1 = ldcs4(&xr[(size_t)4 * D4_]);
    float4 C1 = ldcs4(&xr[(size_t)5 * D4_]);

#pragma unroll
    for (int w = 0; w < CWIN; w++) {
        float4 A2, B2, C2;
        if (w + 2 < CWIN) {                  // prefetch window w+2
            A2 = ldcs4(&xr[(size_t)(3 * (w + 2))     * D4_]);
            B2 = ldcs4(&xr[(size_t)(3 * (w + 2) + 1) * D4_]);
            C2 = ldcs4(&xr[(size_t)(3 * (w + 2) + 2) * D4_]);
        }
        L4[(size_t)w * D4_] = run;                       // keep in L2
        float4 sum = f4add(f4add(A0, B0), C0);           // raw row-sum
        run = f4add(run, sum);
        A0 = A1; B0 = B1; C0 = C1;
        A1 = A2; B1 = B2; C1 = C2;
    }
    ((float4*)g_S)[((size_t)b * NCH + c) * D4_ + i] = run;
}

// ---------------------------------------------------------------------------
// 1b) Win rows from chunk-local prefixes (depends ONLY on fused; runs on
//     stream 2 overlapped with scan+gather):
//     winsum_t = (j<15 ? L[t+1] : S[c]) - L[t],  out[2t+1] = winsum/3.
// ---------------------------------------------------------------------------
__global__ void __launch_bounds__(256) k_win(float4* __restrict__ out) {
    int blk = blockIdx.x;               // 512 blocks = (b, chunk)
    int b = blk >> 6, c = blk & 63;
    int q0 = c * CWIN;
    int i = threadIdx.x;

    const float4* L4 = (const float4*)g_L + ((size_t)b * (STEPS + 1) + q0) * D4_ + i;
    float4 Sc = ((const float4*)g_S)[((size_t)b * NCH + c) * D4_ + i];
    float4* o4 = out + ((size_t)(b * 2 * STEPS) + 2 * q0 + 1) * D4_ + i;

    const float inv3 = 1.0f / 3.0f;
    float4 cur = L4[0];                                  // = 0 vector
#pragma unroll
    for (int j = 0; j < CWIN; j++) {
        float4 nxt = (j < CWIN - 1) ? L4[(size_t)(j + 1) * D4_] : Sc;
        float4 d = f4sub(nxt, cur);
        stcs4(&o4[(size_t)(2 * j) * D4_],
              make_float4(d.x * inv3, d.y * inv3, d.z * inv3, d.w * inv3));
        cur = nxt;
    }
}

// ---------------------------------------------------------------------------
// 2) Hierarchical scan of 64 chunk totals: 512 blocks = b(8) x d-tile(64 of
//    16 d). Block: 16 d-lanes x 16 groups; each thread sums 4 chunks (MLP=4),
//    shared 16-way exclusive scan per d-lane, emits its 4 SP entries.
// ---------------------------------------------------------------------------
__global__ void __launch_bounds__(256) k_scan() {
    __shared__ float sh[16][16];
    int blk = blockIdx.x;               // 512 blocks
    int b = blk >> 6, dt = blk & 63;
    int dl = threadIdx.x & 15;          // d-lane within tile
    int gr = threadIdx.x >> 4;          // chunk group 0..15
    int d = dt * 16 + dl;

    const float* S = g_S + (size_t)b * NCH * D_ + d;
    float v[4];
#pragma unroll
    for (int j = 0; j < 4; j++) v[j] = S[(size_t)(gr * 4 + j) * D_];
    float gsum = (v[0] + v[1]) + (v[2] + v[3]);
    sh[gr][dl] = gsum;
    __syncthreads();

    float off = 0.f;
#pragma unroll
    for (int j = 0; j < 16; j++) { float t = sh[j][dl]; if (j < gr) off += t; }

    float* SPp = g_SP + (size_t)b * (NCH + 1) * D_ + d;
    float run = off;
#pragma unroll
    for (int j = 0; j < 4; j++) {
        SPp[(size_t)(gr * 4 + j) * D_] = run;
        run += v[j];
    }
    if (gr == 15) {
        SPp[(size_t)NCH * D_] = run;                              // SP[64] = total
        g_L[((size_t)b * (STEPS + 1) + STEPS) * D_ + d] = 0.f;    // L[q=STEPS] = 0
    }
}

// ---------------------------------------------------------------------------
// 3) Gather, 2 segments per block, indices PRECOMPUTED (one hot int4 load
//    replaces the graph parse): pref(q) = SP[q>>4] + L[q]; residual x rows
//    use default caching (cross-segment row reuse).
// ---------------------------------------------------------------------------
__global__ void __launch_bounds__(256) k_gather(const float4* __restrict__ x,
                                                float4* __restrict__ out) {
    int blk = blockIdx.x;               // 4096 blocks
    int b = blk >> 9, tp = blk & 511;
    int bt0 = (b << 10) + 2 * tp;       // segment indices bt0, bt0+1
    int i = threadIdx.x;

    int4 w0 = g_idx[bt0];
    int4 w1 = g_idx[bt0 + 1];
    float inv0 = g_inv[bt0];
    float inv1 = g_inv[bt0 + 1];

    const float4* L4  = (const float4*)g_L  + (size_t)b * (STEPS + 1) * D4_;
    const float4* SP4 = (const float4*)g_SP + (size_t)b * (NCH + 1) * D4_;
    const float4* x4  = x + (size_t)b * N_ * D4_;

    // 8 independent prefix loads in flight
    float4 Le0 = L4[(size_t)w0.x * D4_ + i];
    float4 Ls0 = L4[(size_t)w0.z * D4_ + i];
    float4 Le1 = L4[(size_t)w1.x * D4_ + i];
    float4 Ls1 = L4[(size_t)w1.z * D4_ + i];
    float4 Pe0 = SP4[(size_t)(w0.x >> 4) * D4_ + i];
    float4 Ps0 = SP4[(size_t)(w0.z >> 4) * D4_ + i];
    float4 Pe1 = SP4[(size_t)(w1.x >> 4) * D4_ + i];
    float4 Ps1 = SP4[(size_t)(w1.z >> 4) * D4_ + i];

    float4 acc0 = f4sub(f4add(Le0, Pe0), f4add(Ls0, Ps0));
    float4 acc1 = f4sub(f4add(Le1, Pe1), f4add(Ls1, Ps1));

    if (w0.y != 0) {
        int row = (w0.y > 0 ? w0.y : -w0.y) - 1;
        float sgn = (w0.y > 0) ? 1.f : -1.f;
        float4 v = x4[(size_t)row * D4_ + i];
        acc0 = make_float4(fmaf(sgn, v.x, acc0.x), fmaf(sgn, v.y, acc0.y),
                           fmaf(sgn, v.z, acc0.z), fmaf(sgn, v.w, acc0.w));
    }
    if (w0.w != 0) {
        int row = (w0.w > 0 ? w0.w : -w0.w) - 1;
        float sgn = (w0.w > 0) ? 1.f : -1.f;
        float4 v = x4[(size_t)row * D4_ + i];
        acc0 = make_float4(fmaf(sgn, v.x, acc0.x), fmaf(sgn, v.y, acc0.y),
                           fmaf(sgn, v.z, acc0.z), fmaf(sgn, v.w, acc0.w));
    }
    if (w1.y != 0) {
        int row = (w1.y > 0 ? w1.y : -w1.y) - 1;
        float sgn = (w1.y > 0) ? 1.f : -1.f;
        float4 v = x4[(size_t)row * D4_ + i];
        acc1 = make_float4(fmaf(sgn, v.x, acc1.x), fmaf(sgn, v.y, acc1.y),
                           fmaf(sgn, v.z, acc1.z), fmaf(sgn, v.w, acc1.w));
    }
    if (w1.w != 0) {
        int row = (w1.w > 0 ? w1.w : -w1.w) - 1;
        float sgn = (w1.w > 0) ? 1.f : -1.f;
        float4 v = x4[(size_t)row * D4_ + i];
        acc1 = make_float4(fmaf(sgn, v.x, acc1.x), fmaf(sgn, v.y, acc1.y),
                           fmaf(sgn, v.z, acc1.z), fmaf(sgn, v.w, acc1.w));
    }

    float4 o0 = make_float4(acc0.x * inv0 + EPS_, acc0.y * inv0 + EPS_,
                            acc0.z * inv0 + EPS_, acc0.w * inv0 + EPS_);
    float4 o1 = make_float4(acc1.x * inv1 + EPS_, acc1.y * inv1 + EPS_,
                            acc1.z * inv1 + EPS_, acc1.w * inv1 + EPS_);
    stcs4(&out[(size_t)(2 * bt0) * D4_ + i], o0);
    stcs4(&out[(size_t)(2 * bt0 + 2) * D4_ + i], o1);
}

// ---------------------------------------------------------------------------
// Launch topology (capture-legal fork/join):
//   main: [evStart] k_fused [evFork] (wait evPrep) k_scan k_gather (wait evJoin)
//   s2  : (wait evStart) k_prep [evPrep] (wait evFork) k_win [evJoin]
// s2 joins the capture via evStart BEFORE its first launch (capture rule).
// ---------------------------------------------------------------------------
extern "C" void kernel_launch(void* const* d_in, const int* in_sizes, int n_in,
                              void* d_out, int out_size) {
    const float* x     = (const float*)d_in[0];
    const void*  graph = d_in[1];
    float*       out   = (float*)d_out;

    static cudaStream_t s2 = nullptr;
    static cudaEvent_t evStart = nullptr, evFork = nullptr,
                       evJoin = nullptr, evPrep = nullptr;
    if (s2 == nullptr) {
        cudaStreamCreateWithFlags(&s2, cudaStreamNonBlocking);
        cudaEventCreateWithFlags(&evStart, cudaEventDisableTiming);
        cudaEventCreateWithFlags(&evFork, cudaEventDisableTiming);
        cudaEventCreateWithFlags(&evJoin, cudaEventDisableTiming);
        cudaEventCreateWithFlags(&evPrep, cudaEventDisableTiming);
    }

    cudaEventRecord(evStart, 0);                // fork s2 into the capture
    cudaStreamWaitEvent(s2, evStart, 0);
    k_prep<<<32, 256, 0, s2>>>(graph);          // overlapped with k_fused
    cudaEventRecord(evPrep, s2);

    k_fused<<<B_ * NCH, 256>>>((const float4*)x);

    cudaEventRecord(evFork, 0);                 // fork point after fused
    cudaStreamWaitEvent(s2, evFork, 0);
    k_win<<<B_ * NCH, 256, 0, s2>>>((float4*)out);   // overlapped branch

    cudaStreamWaitEvent(0, evPrep, 0);          // gather needs g_idx/g_inv
    k_scan  <<<512, 256>>>();
    k_gather<<<B_ * STEPS / 2, 256>>>((const float4*)x, (float4*)out);

    cudaEventRecord(evJoin, s2);                // join back to main stream
    cudaStreamWaitEvent(0, evJoin, 0);
}